// round 15
// baseline (speedup 1.0000x reference)
#include <cuda_runtime.h>
#include <cuda_fp16.h>
#include <cstdint>

#define NDIM 16384
#define BDIM 512
#define NNZ  131072
#define U4ROW 64        // 64 uint4 (8 halves each) per column row
#define B4f  (BDIM/4)   // 128 float4 per column (fp32 final h)

// ---------------- device scratch (static allocation; no cudaMalloc) -------------
__device__ __align__(16) __half g_hh0[(size_t)NDIM * BDIM];   // h ping (N,B) fp16
__device__ __align__(16) __half g_hh1[(size_t)NDIM * BDIM];   // h pong (N,B) fp16
__device__ __align__(16) __half g_ch [(size_t)NDIM * BDIM];   // cell state fp16
__device__ __align__(16) float  g_hfinal[(size_t)NDIM * BDIM];// final h fp32 (N,B)
__device__ __align__(16) float4 g_eb[NDIM];                   // {e^-bi, e^-bf, e^-bo, e^-2bg}

__device__ int                g_colcnt[NDIM];
__device__ int                g_colstart[NDIM + 1];
__device__ int                g_cur[NDIM];
__device__ __align__(16) unsigned long long g_pack[NNZ];  // [45:32]=row [31:0]=val bits
__device__ int                g_idx_nonzero_odd = 0;      // monotonic 0->1; pure fn of input

// ---------------- init: zero counters + sampled index-dtype detection ------------
__global__ void k_init(const int* __restrict__ w) {
    int i = blockIdx.x * blockDim.x + threadIdx.x;
    if (i < NDIM) g_colcnt[i] = 0;
    if (i < 4096 && w[2 * i + 1] != 0) atomicOr(&g_idx_nonzero_odd, 1);
}

__device__ __forceinline__ void load_rc(const void* idx, int e, int& row, int& col) {
    if (g_idx_nonzero_odd) {               // int32 pairs
        const int* p = (const int*)idx;
        row = p[2 * e + 0];
        col = p[2 * e + 1];
    } else {                               // int64 pairs
        const long long* p = (const long long*)idx;
        row = (int)p[2 * e + 0];
        col = (int)p[2 * e + 1];
    }
    row &= (NDIM - 1);
    col &= (NDIM - 1);
}

__global__ void k_hist(const void* __restrict__ idx) {
    int e = blockIdx.x * blockDim.x + threadIdx.x;
    if (e < NNZ) {
        int row, col;
        load_rc(idx, e, row, col);
        atomicAdd(&g_colcnt[col], 1);
    }
}

// 1024 threads, 1 block: int4 loads, shfl warp scan + block scan over warp sums
__global__ void __launch_bounds__(1024) k_scan() {
    __shared__ int ws[32];
    int t = threadIdx.x;                 // 0..1023, owns 16 consecutive bins
    const int4* cc = (const int4*)g_colcnt;
    int4 a0 = cc[t * 4 + 0], a1 = cc[t * 4 + 1], a2 = cc[t * 4 + 2], a3 = cc[t * 4 + 3];
    int v[16] = {a0.x, a0.y, a0.z, a0.w, a1.x, a1.y, a1.z, a1.w,
                 a2.x, a2.y, a2.z, a2.w, a3.x, a3.y, a3.z, a3.w};
    int tot = 0;
    #pragma unroll
    for (int k = 0; k < 16; k++) tot += v[k];

    int lane = t & 31, w = t >> 5;
    int sc = tot;
    #pragma unroll
    for (int off = 1; off < 32; off <<= 1) {
        int n = __shfl_up_sync(0xffffffffu, sc, off);
        if (lane >= off) sc += n;
    }
    if (lane == 31) ws[w] = sc;
    __syncthreads();
    if (w == 0) {
        int x = ws[lane];
        #pragma unroll
        for (int off = 1; off < 32; off <<= 1) {
            int n = __shfl_up_sync(0xffffffffu, x, off);
            if (lane >= off) x += n;
        }
        ws[lane] = x;
    }
    __syncthreads();
    int base = (w ? ws[w - 1] : 0) + (sc - tot);
    #pragma unroll
    for (int k = 0; k < 16; k++) {
        g_colstart[t * 16 + k] = base;
        g_cur[t * 16 + k] = base;
        base += v[k];
    }
    if (t == 1023) g_colstart[NDIM] = base;   // == NNZ
}

__global__ void k_scatter(const void* __restrict__ idx,
                          const float* __restrict__ vals) {
    int e = blockIdx.x * blockDim.x + threadIdx.x;
    if (e < NNZ) {
        int row, col;
        load_rc(idx, e, row, col);
        int pos = atomicAdd(&g_cur[col], 1);
        unsigned long long p = ((unsigned long long)(unsigned)row << 32)
                             | (unsigned)__float_as_int(vals[e]);
        g_pack[pos] = p;
    }
}

// ---------------- precompute bias exponentials -----------------------------------
__global__ void k_ebias(const float* __restrict__ bi_, const float* __restrict__ bf_,
                        const float* __restrict__ bo_, const float* __restrict__ bg_) {
    int col = blockIdx.x * blockDim.x + threadIdx.x;
    if (col < NDIM) {
        g_eb[col] = make_float4(__expf(-bi_[col]), __expf(-bf_[col]),
                                __expf(-bo_[col]), __expf(-2.0f * bg_[col]));
    }
}

// ---------------- transpose in: x (B,N) fp32 -> g_hh0 (N,B) fp16 -----------------
__global__ void k_transpose_in(const float* __restrict__ x) {
    __shared__ float tile[32][33];
    int nBase = blockIdx.x * 32;
    int bBase = blockIdx.y * 32;
    int tx = threadIdx.x, ty = threadIdx.y;
    #pragma unroll
    for (int i = ty; i < 32; i += 8)
        tile[i][tx] = x[(size_t)(bBase + i) * NDIM + nBase + tx];
    __syncthreads();
    #pragma unroll
    for (int i = ty; i < 32; i += 8)
        g_hh0[(size_t)(nBase + i) * BDIM + bBase + tx] = __float2half(tile[tx][i]);
}

// ---------------- fused SpMM + LSTM gate iteration ------------------------------
__device__ __forceinline__ float lstm_elem(float z, float& c,
                                           float ebi, float ebf, float ebo, float ebg2) {
    float ez = __expf(-z);
    float i = __fdividef(1.0f, 1.0f + ez * ebi);
    float f = __fdividef(1.0f, 1.0f + ez * ebf);
    float o = __fdividef(1.0f, 1.0f + ez * ebo);
    float w = ez * ez * ebg2;                         // e^{-2(z+b_g)}
    float g = __fdividef(2.0f, 1.0f + w) - 1.0f;      // tanh(z+b_g)
    c = f * c + i * g;
    float ec = __expf(-2.0f * c);
    float th = __fdividef(1.0f - ec, 1.0f + ec);      // tanh(c)
    return o * th;
}

__device__ __forceinline__ void h8_fma(uint4 hr, float v, float* acc) {
    float2 a0 = __half22float2(*(const __half2*)&hr.x);
    float2 a1 = __half22float2(*(const __half2*)&hr.y);
    float2 a2 = __half22float2(*(const __half2*)&hr.z);
    float2 a3 = __half22float2(*(const __half2*)&hr.w);
    acc[0] = fmaf(v, a0.x, acc[0]); acc[1] = fmaf(v, a0.y, acc[1]);
    acc[2] = fmaf(v, a1.x, acc[2]); acc[3] = fmaf(v, a1.y, acc[3]);
    acc[4] = fmaf(v, a2.x, acc[4]); acc[5] = fmaf(v, a2.y, acc[5]);
    acc[6] = fmaf(v, a3.x, acc[6]); acc[7] = fmaf(v, a3.y, acc[7]);
}

// 32 threads/CTA, each thread owns 16 batch elems (two uint4 = 16 halves).
// flip==0: read g_hh0 write g_hh1; flip==1: read g_hh1 write g_hh0.
// first: c starts at 0 (skip load). last: skip c store, write h fp32 into g_hfinal.
__global__ void __launch_bounds__(32, 32)
k_iter(int flip, int first, int last) {
    const uint4* hp = (const uint4*)(flip ? g_hh1 : g_hh0);
    uint4*       hd = (uint4*)(flip ? g_hh0 : g_hh1);
    uint4*       chp = (uint4*)g_ch;

    int col = blockIdx.x;
    int t   = threadIdx.x;                 // 0..31, owns uint4 slots 2t, 2t+1
    int s = g_colstart[col], e = g_colstart[col + 1];

    // issue independent loads early: c state + bias-exp table
    size_t co = (size_t)col * U4ROW + 2 * t;
    uint4  craw0 = make_uint4(0u, 0u, 0u, 0u), craw1 = craw0;
    if (!first) { craw0 = chp[co]; craw1 = chp[co + 1]; }
    float4 eb = g_eb[col];

    float acc[16];
    #pragma unroll
    for (int k = 0; k < 16; k++) acc[k] = 0.f;

    int j = s;
    // 4-deep pipelined main loop: 4 pack loads + 8 uint4 gathers before the FMAs
    for (; j + 4 <= e; j += 4) {
        unsigned long long p0 = g_pack[j + 0];
        unsigned long long p1 = g_pack[j + 1];
        unsigned long long p2 = g_pack[j + 2];
        unsigned long long p3 = g_pack[j + 3];
        size_t b0 = (size_t)((p0 >> 32) & 0x3FFFu) * U4ROW + 2 * t;
        size_t b1 = (size_t)((p1 >> 32) & 0x3FFFu) * U4ROW + 2 * t;
        size_t b2 = (size_t)((p2 >> 32) & 0x3FFFu) * U4ROW + 2 * t;
        size_t b3 = (size_t)((p3 >> 32) & 0x3FFFu) * U4ROW + 2 * t;
        uint4 h0a = hp[b0], h0b = hp[b0 + 1];
        uint4 h1a = hp[b1], h1b = hp[b1 + 1];
        uint4 h2a = hp[b2], h2b = hp[b2 + 1];
        uint4 h3a = hp[b3], h3b = hp[b3 + 1];
        float v0 = __int_as_float((int)(unsigned)p0);
        float v1 = __int_as_float((int)(unsigned)p1);
        float v2 = __int_as_float((int)(unsigned)p2);
        float v3 = __int_as_float((int)(unsigned)p3);
        h8_fma(h0a, v0, acc); h8_fma(h0b, v0, acc + 8);
        h8_fma(h1a, v1, acc); h8_fma(h1b, v1, acc + 8);
        h8_fma(h2a, v2, acc); h8_fma(h2b, v2, acc + 8);
        h8_fma(h3a, v3, acc); h8_fma(h3b, v3, acc + 8);
    }
    for (; j < e; j++) {
        unsigned long long p = g_pack[j];
        size_t b = (size_t)((p >> 32) & 0x3FFFu) * U4ROW + 2 * t;
        uint4 ha = hp[b], hb = hp[b + 1];
        float v = __int_as_float((int)(unsigned)p);
        h8_fma(ha, v, acc); h8_fma(hb, v, acc + 8);
    }

    float cv[16];
    {
        float2 c0 = __half22float2(*(const __half2*)&craw0.x);
        float2 c1 = __half22float2(*(const __half2*)&craw0.y);
        float2 c2 = __half22float2(*(const __half2*)&craw0.z);
        float2 c3 = __half22float2(*(const __half2*)&craw0.w);
        cv[0] = c0.x; cv[1] = c0.y; cv[2] = c1.x; cv[3] = c1.y;
        cv[4] = c2.x; cv[5] = c2.y; cv[6] = c3.x; cv[7] = c3.y;
        float2 c4 = __half22float2(*(const __half2*)&craw1.x);
        float2 c5 = __half22float2(*(const __half2*)&craw1.y);
        float2 c6 = __half22float2(*(const __half2*)&craw1.z);
        float2 c7 = __half22float2(*(const __half2*)&craw1.w);
        cv[8] = c4.x; cv[9] = c4.y; cv[10] = c5.x; cv[11] = c5.y;
        cv[12] = c6.x; cv[13] = c6.y; cv[14] = c7.x; cv[15] = c7.y;
    }

    float hout[16];
    #pragma unroll
    for (int k = 0; k < 16; k++)
        hout[k] = lstm_elem(acc[k], cv[k], eb.x, eb.y, eb.z, eb.w);

    if (last) {
        float4* hf = (float4*)g_hfinal;
        size_t fo = (size_t)col * B4f + 4 * t;
        hf[fo + 0] = make_float4(hout[0],  hout[1],  hout[2],  hout[3]);
        hf[fo + 1] = make_float4(hout[4],  hout[5],  hout[6],  hout[7]);
        hf[fo + 2] = make_float4(hout[8],  hout[9],  hout[10], hout[11]);
        hf[fo + 3] = make_float4(hout[12], hout[13], hout[14], hout[15]);
    } else {
        uint4 cw0, cw1, hw0, hw1;
        *(__half2*)&cw0.x = __floats2half2_rn(cv[0],  cv[1]);
        *(__half2*)&cw0.y = __floats2half2_rn(cv[2],  cv[3]);
        *(__half2*)&cw0.z = __floats2half2_rn(cv[4],  cv[5]);
        *(__half2*)&cw0.w = __floats2half2_rn(cv[6],  cv[7]);
        *(__half2*)&cw1.x = __floats2half2_rn(cv[8],  cv[9]);
        *(__half2*)&cw1.y = __floats2half2_rn(cv[10], cv[11]);
        *(__half2*)&cw1.z = __floats2half2_rn(cv[12], cv[13]);
        *(__half2*)&cw1.w = __floats2half2_rn(cv[14], cv[15]);
        chp[co] = cw0; chp[co + 1] = cw1;
        *(__half2*)&hw0.x = __floats2half2_rn(hout[0],  hout[1]);
        *(__half2*)&hw0.y = __floats2half2_rn(hout[2],  hout[3]);
        *(__half2*)&hw0.z = __floats2half2_rn(hout[4],  hout[5]);
        *(__half2*)&hw0.w = __floats2half2_rn(hout[6],  hout[7]);
        *(__half2*)&hw1.x = __floats2half2_rn(hout[8],  hout[9]);
        *(__half2*)&hw1.y = __floats2half2_rn(hout[10], hout[11]);
        *(__half2*)&hw1.z = __floats2half2_rn(hout[12], hout[13]);
        *(__half2*)&hw1.w = __floats2half2_rn(hout[14], hout[15]);
        hd[co] = hw0; hd[co + 1] = hw1;
    }
}

// ---------------- transpose out: g_hfinal (N,B) fp32 -> out (B,N) ----------------
__global__ void k_transpose_out(float* __restrict__ out) {
    __shared__ float tile[32][33];
    int nBase = blockIdx.x * 32;
    int bBase = blockIdx.y * 32;
    int tx = threadIdx.x, ty = threadIdx.y;
    #pragma unroll
    for (int i = ty; i < 32; i += 8)
        tile[i][tx] = g_hfinal[(size_t)(nBase + i) * BDIM + bBase + tx];
    __syncthreads();
    #pragma unroll
    for (int i = ty; i < 32; i += 8)
        out[(size_t)(bBase + i) * NDIM + nBase + tx] = tile[tx][i];
}

// ---------------- launch ---------------------------------------------------------
extern "C" void kernel_launch(void* const* d_in, const int* in_sizes, int n_in,
                              void* d_out, int out_size) {
    const float* x    = nullptr;
    const float* vals = nullptr;
    const float* bias[4] = {nullptr, nullptr, nullptr, nullptr};
    const void*  idx  = nullptr;
    int nbias = 0;
    for (int i = 0; i < n_in; i++) {
        int sz = in_sizes[i];
        if (sz == NDIM * BDIM)       x = (const float*)d_in[i];
        else if (sz == NNZ)          vals = (const float*)d_in[i];
        else if (sz == NDIM)         { if (nbias < 4) bias[nbias++] = (const float*)d_in[i]; }
        else                         idx = d_in[i];
    }
    float* out = (float*)d_out;
    (void)out_size;

    // build CSC + bias-exp table
    k_init   <<<(NDIM + 255) / 256, 256>>>((const int*)idx);
    k_hist   <<<(NNZ + 255) / 256, 256>>>(idx);
    k_scan   <<<1, 1024>>>();
    k_scatter<<<(NNZ + 255) / 256, 256>>>(idx, vals);
    k_ebias  <<<(NDIM + 255) / 256, 256>>>(bias[0], bias[1], bias[2], bias[3]);

    // state init: h = half(x^T); c handled by `first` flag
    dim3 tb(32, 8);
    dim3 tg(NDIM / 32, BDIM / 32);
    k_transpose_in<<<tg, tb>>>(x);

    // 4 fused iterations; h ping-pong; last writes fp32 into g_hfinal
    k_iter<<<NDIM, 32>>>(0, 1, 0);
    k_iter<<<NDIM, 32>>>(1, 0, 0);
    k_iter<<<NDIM, 32>>>(0, 0, 0);
    k_iter<<<NDIM, 32>>>(1, 0, 1);

    // out (B,N) = transpose(g_hfinal)
    k_transpose_out<<<tg, tb>>>(out);
}

// round 16
// speedup vs baseline: 1.4463x; 1.4463x over previous
#include <cuda_runtime.h>
#include <cuda_fp16.h>
#include <cstdint>

#define NDIM 16384
#define BDIM 512
#define NNZ  131072
#define B8   (BDIM/8)   // 64 uint4 (8 halves) per column
#define B4f  (BDIM/4)   // 128 float4 per column (fp32 final h)

// ---------------- device scratch (static allocation; no cudaMalloc) -------------
__device__ __align__(16) __half g_hh0[(size_t)NDIM * BDIM];   // h ping (N,B) fp16
__device__ __align__(16) __half g_hh1[(size_t)NDIM * BDIM];   // h pong (N,B) fp16
__device__ __align__(16) __half g_ch [(size_t)NDIM * BDIM];   // cell state fp16
__device__ __align__(16) float  g_hfinal[(size_t)NDIM * BDIM];// final h fp32 (N,B)
__device__ __align__(16) float4 g_eb[NDIM];                   // {e^-bi, e^-bf, e^-bo, e^-2bg}

__device__ int                g_colcnt[NDIM];
__device__ int                g_colstart[NDIM + 1];
__device__ int                g_cur[NDIM];
__device__ __align__(16) unsigned long long g_pack[NNZ];  // [45:32]=row [31:0]=val bits
__device__ int                g_idx_nonzero_odd = 0;      // monotonic 0->1; pure fn of input

// ---------------- init: zero counters + sampled index-dtype detection ------------
__global__ void k_init(const int* __restrict__ w) {
    int i = blockIdx.x * blockDim.x + threadIdx.x;
    if (i < NDIM) g_colcnt[i] = 0;
    if (i < 4096 && w[2 * i + 1] != 0) atomicOr(&g_idx_nonzero_odd, 1);
}

__device__ __forceinline__ void load_rc(const void* idx, int e, int& row, int& col) {
    if (g_idx_nonzero_odd) {               // int32 pairs
        const int* p = (const int*)idx;
        row = p[2 * e + 0];
        col = p[2 * e + 1];
    } else {                               // int64 pairs
        const long long* p = (const long long*)idx;
        row = (int)p[2 * e + 0];
        col = (int)p[2 * e + 1];
    }
    row &= (NDIM - 1);
    col &= (NDIM - 1);
}

__global__ void k_hist(const void* __restrict__ idx) {
    int e = blockIdx.x * blockDim.x + threadIdx.x;
    if (e < NNZ) {
        int row, col;
        load_rc(idx, e, row, col);
        atomicAdd(&g_colcnt[col], 1);
    }
}

// 1024 threads, 1 block: int4 loads, shfl warp scan + block scan over warp sums
__global__ void __launch_bounds__(1024) k_scan() {
    __shared__ int ws[32];
    int t = threadIdx.x;                 // 0..1023, owns 16 consecutive bins
    const int4* cc = (const int4*)g_colcnt;
    int4 a0 = cc[t * 4 + 0], a1 = cc[t * 4 + 1], a2 = cc[t * 4 + 2], a3 = cc[t * 4 + 3];
    int v[16] = {a0.x, a0.y, a0.z, a0.w, a1.x, a1.y, a1.z, a1.w,
                 a2.x, a2.y, a2.z, a2.w, a3.x, a3.y, a3.z, a3.w};
    int tot = 0;
    #pragma unroll
    for (int k = 0; k < 16; k++) tot += v[k];

    int lane = t & 31, w = t >> 5;
    int sc = tot;
    #pragma unroll
    for (int off = 1; off < 32; off <<= 1) {
        int n = __shfl_up_sync(0xffffffffu, sc, off);
        if (lane >= off) sc += n;
    }
    if (lane == 31) ws[w] = sc;
    __syncthreads();
    if (w == 0) {
        int x = ws[lane];
        #pragma unroll
        for (int off = 1; off < 32; off <<= 1) {
            int n = __shfl_up_sync(0xffffffffu, x, off);
            if (lane >= off) x += n;
        }
        ws[lane] = x;
    }
    __syncthreads();
    int base = (w ? ws[w - 1] : 0) + (sc - tot);
    #pragma unroll
    for (int k = 0; k < 16; k++) {
        g_colstart[t * 16 + k] = base;
        g_cur[t * 16 + k] = base;
        base += v[k];
    }
    if (t == 1023) g_colstart[NDIM] = base;   // == NNZ
}

__global__ void k_scatter(const void* __restrict__ idx,
                          const float* __restrict__ vals) {
    int e = blockIdx.x * blockDim.x + threadIdx.x;
    if (e < NNZ) {
        int row, col;
        load_rc(idx, e, row, col);
        int pos = atomicAdd(&g_cur[col], 1);
        unsigned long long p = ((unsigned long long)(unsigned)row << 32)
                             | (unsigned)__float_as_int(vals[e]);
        g_pack[pos] = p;
    }
}

// ---------------- precompute bias exponentials -----------------------------------
__global__ void k_ebias(const float* __restrict__ bi_, const float* __restrict__ bf_,
                        const float* __restrict__ bo_, const float* __restrict__ bg_) {
    int col = blockIdx.x * blockDim.x + threadIdx.x;
    if (col < NDIM) {
        g_eb[col] = make_float4(__expf(-bi_[col]), __expf(-bf_[col]),
                                __expf(-bo_[col]), __expf(-2.0f * bg_[col]));
    }
}

// ---------------- transpose in: x (B,N) fp32 -> g_hh0 (N,B) fp16 -----------------
__global__ void k_transpose_in(const float* __restrict__ x) {
    __shared__ float tile[32][33];
    int nBase = blockIdx.x * 32;
    int bBase = blockIdx.y * 32;
    int tx = threadIdx.x, ty = threadIdx.y;
    #pragma unroll
    for (int i = ty; i < 32; i += 8)
        tile[i][tx] = x[(size_t)(bBase + i) * NDIM + nBase + tx];
    __syncthreads();
    #pragma unroll
    for (int i = ty; i < 32; i += 8)
        g_hh0[(size_t)(nBase + i) * BDIM + bBase + tx] = __float2half(tile[tx][i]);
}

// ---------------- fused SpMM + LSTM gate iteration ------------------------------
__device__ __forceinline__ float lstm_elem(float z, float& c,
                                           float ebi, float ebf, float ebo, float ebg2) {
    float ez = __expf(-z);
    float i = __fdividef(1.0f, 1.0f + ez * ebi);
    float f = __fdividef(1.0f, 1.0f + ez * ebf);
    float o = __fdividef(1.0f, 1.0f + ez * ebo);
    float w = ez * ez * ebg2;                         // e^{-2(z+b_g)}
    float g = __fdividef(2.0f, 1.0f + w) - 1.0f;      // tanh(z+b_g)
    c = f * c + i * g;
    float ec = __expf(-2.0f * c);
    float th = __fdividef(1.0f - ec, 1.0f + ec);      // tanh(c)
    return o * th;
}

__device__ __forceinline__ void h8_fma(uint4 hr, float v, float* acc) {
    float2 a0 = __half22float2(*(const __half2*)&hr.x);
    float2 a1 = __half22float2(*(const __half2*)&hr.y);
    float2 a2 = __half22float2(*(const __half2*)&hr.z);
    float2 a3 = __half22float2(*(const __half2*)&hr.w);
    acc[0] = fmaf(v, a0.x, acc[0]); acc[1] = fmaf(v, a0.y, acc[1]);
    acc[2] = fmaf(v, a1.x, acc[2]); acc[3] = fmaf(v, a1.y, acc[3]);
    acc[4] = fmaf(v, a2.x, acc[4]); acc[5] = fmaf(v, a2.y, acc[5]);
    acc[6] = fmaf(v, a3.x, acc[6]); acc[7] = fmaf(v, a3.y, acc[7]);
}

// 64 threads/CTA, each thread owns 8 batch elems (one uint4 = 8 halves).
// flip==0: read g_hh0 write g_hh1; flip==1: read g_hh1 write g_hh0.
// first: c starts at 0 (skip load). last: skip c store, write h fp32 into g_hfinal.
__global__ void __launch_bounds__(64)
k_iter(int flip, int first, int last) {
    const uint4* hp = (const uint4*)(flip ? g_hh1 : g_hh0);
    uint4*       hd = (uint4*)(flip ? g_hh0 : g_hh1);
    uint4*       chp = (uint4*)g_ch;

    int col = blockIdx.x;
    int t   = threadIdx.x;                 // 0..63
    int s = g_colstart[col], e = g_colstart[col + 1];

    // issue independent loads early: c state + bias-exp table
    size_t co = (size_t)col * B8 + t;
    uint4  craw = make_uint4(0u, 0u, 0u, 0u);
    if (!first) craw = chp[co];
    float4 eb = g_eb[col];

    float acc[8] = {0.f, 0.f, 0.f, 0.f, 0.f, 0.f, 0.f, 0.f};
    int j = s;
    // 8-deep pipelined main loop: 8 pack loads + 8 gathers before the FMAs
    // (avg column degree is 8 -> one batch typically covers the whole column)
    for (; j + 8 <= e; j += 8) {
        unsigned long long p0 = g_pack[j + 0];
        unsigned long long p1 = g_pack[j + 1];
        unsigned long long p2 = g_pack[j + 2];
        unsigned long long p3 = g_pack[j + 3];
        unsigned long long p4 = g_pack[j + 4];
        unsigned long long p5 = g_pack[j + 5];
        unsigned long long p6 = g_pack[j + 6];
        unsigned long long p7 = g_pack[j + 7];
        uint4 h0 = hp[(size_t)((p0 >> 32) & 0x3FFFu) * B8 + t];
        uint4 h1 = hp[(size_t)((p1 >> 32) & 0x3FFFu) * B8 + t];
        uint4 h2 = hp[(size_t)((p2 >> 32) & 0x3FFFu) * B8 + t];
        uint4 h3 = hp[(size_t)((p3 >> 32) & 0x3FFFu) * B8 + t];
        uint4 h4 = hp[(size_t)((p4 >> 32) & 0x3FFFu) * B8 + t];
        uint4 h5 = hp[(size_t)((p5 >> 32) & 0x3FFFu) * B8 + t];
        uint4 h6 = hp[(size_t)((p6 >> 32) & 0x3FFFu) * B8 + t];
        uint4 h7 = hp[(size_t)((p7 >> 32) & 0x3FFFu) * B8 + t];
        h8_fma(h0, __int_as_float((int)(unsigned)p0), acc);
        h8_fma(h1, __int_as_float((int)(unsigned)p1), acc);
        h8_fma(h2, __int_as_float((int)(unsigned)p2), acc);
        h8_fma(h3, __int_as_float((int)(unsigned)p3), acc);
        h8_fma(h4, __int_as_float((int)(unsigned)p4), acc);
        h8_fma(h5, __int_as_float((int)(unsigned)p5), acc);
        h8_fma(h6, __int_as_float((int)(unsigned)p6), acc);
        h8_fma(h7, __int_as_float((int)(unsigned)p7), acc);
    }
    for (; j + 4 <= e; j += 4) {
        unsigned long long p0 = g_pack[j + 0];
        unsigned long long p1 = g_pack[j + 1];
        unsigned long long p2 = g_pack[j + 2];
        unsigned long long p3 = g_pack[j + 3];
        uint4 h0 = hp[(size_t)((p0 >> 32) & 0x3FFFu) * B8 + t];
        uint4 h1 = hp[(size_t)((p1 >> 32) & 0x3FFFu) * B8 + t];
        uint4 h2 = hp[(size_t)((p2 >> 32) & 0x3FFFu) * B8 + t];
        uint4 h3 = hp[(size_t)((p3 >> 32) & 0x3FFFu) * B8 + t];
        h8_fma(h0, __int_as_float((int)(unsigned)p0), acc);
        h8_fma(h1, __int_as_float((int)(unsigned)p1), acc);
        h8_fma(h2, __int_as_float((int)(unsigned)p2), acc);
        h8_fma(h3, __int_as_float((int)(unsigned)p3), acc);
    }
    for (; j < e; j++) {
        unsigned long long p = g_pack[j];
        uint4 hr = hp[(size_t)((p >> 32) & 0x3FFFu) * B8 + t];
        h8_fma(hr, __int_as_float((int)(unsigned)p), acc);
    }

    float cv[8];
    {
        float2 c0 = __half22float2(*(const __half2*)&craw.x);
        float2 c1 = __half22float2(*(const __half2*)&craw.y);
        float2 c2 = __half22float2(*(const __half2*)&craw.z);
        float2 c3 = __half22float2(*(const __half2*)&craw.w);
        cv[0] = c0.x; cv[1] = c0.y; cv[2] = c1.x; cv[3] = c1.y;
        cv[4] = c2.x; cv[5] = c2.y; cv[6] = c3.x; cv[7] = c3.y;
    }

    float hout[8];
    #pragma unroll
    for (int k = 0; k < 8; k++)
        hout[k] = lstm_elem(acc[k], cv[k], eb.x, eb.y, eb.z, eb.w);

    if (last) {
        float4* hf = (float4*)g_hfinal;
        size_t fo = (size_t)col * B4f + 2 * t;
        hf[fo + 0] = make_float4(hout[0], hout[1], hout[2], hout[3]);
        hf[fo + 1] = make_float4(hout[4], hout[5], hout[6], hout[7]);
    } else {
        uint4 cw;
        *(__half2*)&cw.x = __floats2half2_rn(cv[0], cv[1]);
        *(__half2*)&cw.y = __floats2half2_rn(cv[2], cv[3]);
        *(__half2*)&cw.z = __floats2half2_rn(cv[4], cv[5]);
        *(__half2*)&cw.w = __floats2half2_rn(cv[6], cv[7]);
        chp[co] = cw;
        uint4 hw;
        *(__half2*)&hw.x = __floats2half2_rn(hout[0], hout[1]);
        *(__half2*)&hw.y = __floats2half2_rn(hout[2], hout[3]);
        *(__half2*)&hw.z = __floats2half2_rn(hout[4], hout[5]);
        *(__half2*)&hw.w = __floats2half2_rn(hout[6], hout[7]);
        hd[co] = hw;
    }
}

// ---------------- transpose out: g_hfinal (N,B) fp32 -> out (B,N) ----------------
__global__ void k_transpose_out(float* __restrict__ out) {
    __shared__ float tile[32][33];
    int nBase = blockIdx.x * 32;
    int bBase = blockIdx.y * 32;
    int tx = threadIdx.x, ty = threadIdx.y;
    #pragma unroll
    for (int i = ty; i < 32; i += 8)
        tile[i][tx] = g_hfinal[(size_t)(nBase + i) * BDIM + bBase + tx];
    __syncthreads();
    #pragma unroll
    for (int i = ty; i < 32; i += 8)
        out[(size_t)(bBase + i) * NDIM + nBase + tx] = tile[tx][i];
}

// ---------------- launch ---------------------------------------------------------
extern "C" void kernel_launch(void* const* d_in, const int* in_sizes, int n_in,
                              void* d_out, int out_size) {
    const float* x    = nullptr;
    const float* vals = nullptr;
    const float* bias[4] = {nullptr, nullptr, nullptr, nullptr};
    const void*  idx  = nullptr;
    int nbias = 0;
    for (int i = 0; i < n_in; i++) {
        int sz = in_sizes[i];
        if (sz == NDIM * BDIM)       x = (const float*)d_in[i];
        else if (sz == NNZ)          vals = (const float*)d_in[i];
        else if (sz == NDIM)         { if (nbias < 4) bias[nbias++] = (const float*)d_in[i]; }
        else                         idx = d_in[i];
    }
    float* out = (float*)d_out;
    (void)out_size;

    // build CSC + bias-exp table
    k_init   <<<(NDIM + 255) / 256, 256>>>((const int*)idx);
    k_hist   <<<(NNZ + 255) / 256, 256>>>(idx);
    k_scan   <<<1, 1024>>>();
    k_scatter<<<(NNZ + 255) / 256, 256>>>(idx, vals);
    k_ebias  <<<(NDIM + 255) / 256, 256>>>(bias[0], bias[1], bias[2], bias[3]);

    // state init: h = half(x^T); c handled by `first` flag
    dim3 tb(32, 8);
    dim3 tg(NDIM / 32, BDIM / 32);
    k_transpose_in<<<tg, tb>>>(x);

    // 4 fused iterations; h ping-pong; last writes fp32 into g_hfinal
    k_iter<<<NDIM, 64>>>(0, 1, 0);
    k_iter<<<NDIM, 64>>>(1, 0, 0);
    k_iter<<<NDIM, 64>>>(0, 0, 0);
    k_iter<<<NDIM, 64>>>(1, 0, 1);

    // out (B,N) = transpose(g_hfinal)
    k_transpose_out<<<tg, tb>>>(out);
}